// round 6
// baseline (speedup 1.0000x reference)
#include <cuda_runtime.h>

#define T_CACHE 1024
#define ROW3C   3072
#define CEMB    1024
#define BQ      64          // queries per phase
#define BK      32          // keys per smem tile
#define CH      8           // score-chunk size
#define NTH     128
#define NB      32          // number of 64-query blocks (2048/64)
#define NPAIR   16          // balanced pairs

typedef unsigned long long u64;

__device__ __forceinline__ u64 fma2(u64 a, u64 b, u64 c) {
    u64 d; asm("fma.rn.f32x2 %0, %1, %2, %3;" : "=l"(d) : "l"(a), "l"(b), "l"(c)); return d;
}
__device__ __forceinline__ u64 mul2(u64 a, u64 b) {
    u64 d; asm("mul.rn.f32x2 %0, %1, %2;" : "=l"(d) : "l"(a), "l"(b)); return d;
}
__device__ __forceinline__ u64 pack2(float x) {
    u64 d; asm("mov.b64 %0, {%1, %1};" : "=l"(d) : "f"(x)); return d;
}
__device__ __forceinline__ u64 pack2p(float x, float y) {
    u64 d; asm("mov.b64 %0, {%1, %2};" : "=l"(d) : "f"(x), "f"(y)); return d;
}
__device__ __forceinline__ float hadd2(u64 a) {
    float lo, hi; asm("mov.b64 {%0, %1}, %2;" : "=f"(lo), "=f"(hi) : "l"(a)); return lo + hi;
}

// Process one CH-key chunk of the current tile.
template<bool MASK>
__device__ __forceinline__ void do_chunk(
    const ulonglong2* __restrict__ ksm, const ulonglong2* __restrict__ vsm,
    int c0, int s0, int sub, int tq0,
    const u64 q[2][8], u64 acc[2][8], float m[2], float l[2])
{
    float sc[2][CH];

#pragma unroll
    for (int j = 0; j < CH; ++j) {
        const int jj = c0 + j;
        const ulonglong2 ka = ksm[jj * 16 + sub];
        const ulonglong2 kb = ksm[jj * 16 + sub + 4];
        const ulonglong2 kc = ksm[jj * 16 + sub + 8];
        const ulonglong2 kd = ksm[jj * 16 + sub + 12];
#pragma unroll
        for (int qq = 0; qq < 2; ++qq) {
            u64 t = mul2(q[qq][0], ka.x);
            t = fma2(q[qq][1], ka.y, t);
            t = fma2(q[qq][2], kb.x, t);
            t = fma2(q[qq][3], kb.y, t);
            t = fma2(q[qq][4], kc.x, t);
            t = fma2(q[qq][5], kc.y, t);
            t = fma2(q[qq][6], kd.x, t);
            t = fma2(q[qq][7], kd.y, t);
            float s = hadd2(t);
            s += __shfl_xor_sync(0xffffffffu, s, 1);
            s += __shfl_xor_sync(0xffffffffu, s, 2);
            if (MASK)
                sc[qq][j] = (s0 + jj <= tq0 + qq) ? s : -1e30f;
            else
                sc[qq][j] = s;
        }
    }

    // online softmax update
#pragma unroll
    for (int qq = 0; qq < 2; ++qq) {
        float bm = sc[qq][0];
#pragma unroll
        for (int j = 1; j < CH; ++j) bm = fmaxf(bm, sc[qq][j]);
        const float mn = fmaxf(m[qq], bm);
        const float al = __expf(m[qq] - mn);
        m[qq] = mn;
        l[qq] *= al;
        const u64 al2 = pack2(al);
#pragma unroll
        for (int u = 0; u < 8; ++u) acc[qq][u] = mul2(acc[qq][u], al2);
#pragma unroll
        for (int j = 0; j < CH; ++j) {
            const float p = __expf(sc[qq][j] - mn);
            l[qq] += p;
            sc[qq][j] = p;
        }
    }

    // PV accumulate
#pragma unroll
    for (int j = 0; j < CH; ++j) {
        const int jj = c0 + j;
        const ulonglong2 va = vsm[jj * 16 + sub];
        const ulonglong2 vb = vsm[jj * 16 + sub + 4];
        const ulonglong2 vc = vsm[jj * 16 + sub + 8];
        const ulonglong2 vd = vsm[jj * 16 + sub + 12];
#pragma unroll
        for (int qq = 0; qq < 2; ++qq) {
            const u64 p2 = pack2(sc[qq][j]);
            acc[qq][0] = fma2(p2, va.x, acc[qq][0]);
            acc[qq][1] = fma2(p2, va.y, acc[qq][1]);
            acc[qq][2] = fma2(p2, vb.x, acc[qq][2]);
            acc[qq][3] = fma2(p2, vb.y, acc[qq][3]);
            acc[qq][4] = fma2(p2, vc.x, acc[qq][4]);
            acc[qq][5] = fma2(p2, vc.y, acc[qq][5]);
            acc[qq][6] = fma2(p2, vd.x, acc[qq][6]);
            acc[qq][7] = fma2(p2, vd.y, acc[qq][7]);
        }
    }
}

// One 64-query block (one "phase") done by the whole CTA.
__device__ __forceinline__ void run_phase(
    int qb, int h,
    const float* __restrict__ qkv, const float* __restrict__ cache,
    float* __restrict__ out,
    ulonglong2* ksm, ulonglong2* vsm, int tid)
{
    const int sub = tid & 3;      // 16-dim slice: float4 chunks {sub, sub+4, sub+8, sub+12}
    const int grp = tid >> 2;     // 0..31 -> 2 queries each
    const int ql  = qb * BQ + grp * 2;   // local query row (0..2047)
    const int tq0 = T_CACHE + ql;        // global position of qq=0

    // load + pre-scale q
    const float scl = 0.125f;
    u64 q[2][8];
#pragma unroll
    for (int qq = 0; qq < 2; ++qq) {
        const float4* qr = reinterpret_cast<const float4*>(
            qkv + (size_t)(ql + qq) * ROW3C + h * 64);
#pragma unroll
        for (int i = 0; i < 4; ++i) {
            float4 v = qr[sub + 4 * i];
            q[qq][2 * i]     = pack2p(v.x * scl, v.y * scl);
            q[qq][2 * i + 1] = pack2p(v.z * scl, v.w * scl);
        }
    }

    u64 acc[2][8];
#pragma unroll
    for (int qq = 0; qq < 2; ++qq)
#pragma unroll
        for (int u = 0; u < 8; ++u) acc[qq][u] = 0ull;
    float m[2] = {-1e30f, -1e30f};
    float l[2] = {0.f, 0.f};

    const int nkeys  = T_CACHE + qb * BQ + BQ;
    const int ntiles = nkeys / BK;      // exact
    const int nfull  = ntiles - 2;      // last BQ keys need the causal mask

    for (int t = 0; t < ntiles; ++t) {
        const int s0 = t * BK;
        __syncthreads();
        // tiles never straddle the cache/qkv boundary (1024 % 32 == 0)
        const float* base = (s0 < T_CACHE)
            ? (cache + (size_t)s0 * ROW3C)
            : (qkv + (size_t)(s0 - T_CACHE) * ROW3C);
#pragma unroll
        for (int it = 0; it < 4; ++it) {
            const int idx = tid + it * NTH;   // 0..511
            const int row = idx >> 4;
            const int c   = idx & 15;
            const float* rp = base + (size_t)row * ROW3C + h * 64 + c * 4;
            ksm[idx] = *reinterpret_cast<const ulonglong2*>(rp + CEMB);
            vsm[idx] = *reinterpret_cast<const ulonglong2*>(rp + 2 * CEMB);
        }
        __syncthreads();

        if (t < nfull) {
#pragma unroll
            for (int c0 = 0; c0 < BK; c0 += CH)
                do_chunk<false>(ksm, vsm, c0, s0, sub, tq0, q, acc, m, l);
        } else {
#pragma unroll
            for (int c0 = 0; c0 < BK; c0 += CH)
                do_chunk<true>(ksm, vsm, c0, s0, sub, tq0, q, acc, m, l);
        }
    }

    // epilogue
#pragma unroll
    for (int qq = 0; qq < 2; ++qq) {
        const u64 inv2 = pack2(1.f / l[qq]);
        ulonglong2* orow = reinterpret_cast<ulonglong2*>(
            out + (size_t)(ql + qq) * CEMB + h * 64);
#pragma unroll
        for (int i = 0; i < 4; ++i) {
            ulonglong2 o;
            o.x = mul2(acc[qq][2 * i], inv2);
            o.y = mul2(acc[qq][2 * i + 1], inv2);
            orow[sub + 4 * i] = o;
        }
    }
}

__global__ __launch_bounds__(NTH, 3)
void fa2_kernel(const float* __restrict__ qkv,
                const float* __restrict__ cache,
                float* __restrict__ out)
{
    __shared__ ulonglong2 ksm[BK * 16];
    __shared__ ulonglong2 vsm[BK * 16];

    const int qbp = blockIdx.x;   // 0..15
    const int h   = blockIdx.y;   // 0..15
    const int tid = threadIdx.x;

    // balanced pair: (qbp) + (31 - qbp) => constant 130 tiles per CTA
    run_phase(qbp, h, qkv, cache, out, ksm, vsm, tid);
    run_phase(NB - 1 - qbp, h, qkv, cache, out, ksm, vsm, tid);
}

extern "C" void kernel_launch(void* const* d_in, const int* in_sizes, int n_in,
                              void* d_out, int out_size)
{
    const float* qkv   = (const float*)d_in[0];   // [2048, 3072]
    const float* cache = (const float*)d_in[1];   // [1024, 3072]
    float* out = (float*)d_out;                   // [2048, 1024]

    dim3 grid(NPAIR, 16);    // (16 pairs, 16 heads)
    fa2_kernel<<<grid, NTH>>>(qkv, cache, out);
}

// round 8
// speedup vs baseline: 3.6411x; 3.6411x over previous
#include <cuda_runtime.h>
#include <cuda_bf16.h>
#include <cstdint>

#define ROW3C  3072
#define CEMB   1024
#define BQ     64
#define BK     64
#define NTH    128
#define LDK    72     // padded row length in bf16 elems (144 B) -> conflict-free B frags

__device__ __forceinline__ float ex2f(float x) {
    float y; asm("ex2.approx.f32 %0, %1;" : "=f"(y) : "f"(x)); return y;
}
// res.lo = bf16(a), res.hi = bf16(b)
#define CVTB2(res, a, b) \
    asm("cvt.rn.bf16x2.f32 %0, %1, %2;" : "=r"(res) : "f"(b), "f"(a))

__device__ __forceinline__ void mma16816(float c[4],
    uint32_t a0, uint32_t a1, uint32_t a2, uint32_t a3,
    uint32_t b0, uint32_t b1)
{
    asm volatile(
        "mma.sync.aligned.m16n8k16.row.col.f32.bf16.bf16.f32 "
        "{%0,%1,%2,%3}, {%4,%5,%6,%7}, {%8,%9}, {%0,%1,%2,%3};"
        : "+f"(c[0]), "+f"(c[1]), "+f"(c[2]), "+f"(c[3])
        : "r"(a0), "r"(a1), "r"(a2), "r"(a3), "r"(b0), "r"(b1));
}

__global__ __launch_bounds__(NTH, 2)
void fa_mma_kernel(const float* __restrict__ qkv,
                   const float* __restrict__ cache,
                   float* __restrict__ out)
{
    __shared__ __align__(16) uint16_t KHI[BK * LDK];
    __shared__ __align__(16) uint16_t KLO[BK * LDK];
    __shared__ __align__(16) uint16_t VHI[64 * LDK];   // transposed: [dim][key]
    __shared__ __align__(16) uint16_t VLO[64 * LDK];

    const int tid  = threadIdx.x;
    const int w    = tid >> 5;
    const int lane = tid & 31;
    const int l4   = lane >> 2;        // 0..7
    const int lq2  = (lane & 3) * 2;   // 0,2,4,6
    const int h    = blockIdx.y;
    const int bx   = blockIdx.x;

    for (int phse = 0; phse < 2; ++phse) {
        const int qb = phse ? (31 - bx) : bx;

        // ---- load Q fragments (held in regs for whole phase) ----
        const float scl = 0.125f * 1.44269504f;   // 1/sqrt(64) * log2(e)
        const int r0 = qb * BQ + w * 16 + l4;     // local out row (rows r0, r0+8)
        uint32_t qh[4][4], ql[4][4];
        {
            const float* q0 = qkv + (size_t)r0 * ROW3C + h * 64;
            const float* q1 = q0 + 8 * ROW3C;
#pragma unroll
            for (int kt = 0; kt < 4; ++kt) {
                float2 f0 = *(const float2*)(q0 + kt * 16 + lq2);
                float2 f1 = *(const float2*)(q1 + kt * 16 + lq2);
                float2 f2 = *(const float2*)(q0 + kt * 16 + 8 + lq2);
                float2 f3 = *(const float2*)(q1 + kt * 16 + 8 + lq2);
                f0.x *= scl; f0.y *= scl; f1.x *= scl; f1.y *= scl;
                f2.x *= scl; f2.y *= scl; f3.x *= scl; f3.y *= scl;
                CVTB2(qh[kt][0], f0.x, f0.y);
                CVTB2(qh[kt][1], f1.x, f1.y);
                CVTB2(qh[kt][2], f2.x, f2.y);
                CVTB2(qh[kt][3], f3.x, f3.y);
                CVTB2(ql[kt][0], f0.x - __uint_as_float(qh[kt][0] << 16),
                                 f0.y - __uint_as_float(qh[kt][0] & 0xFFFF0000u));
                CVTB2(ql[kt][1], f1.x - __uint_as_float(qh[kt][1] << 16),
                                 f1.y - __uint_as_float(qh[kt][1] & 0xFFFF0000u));
                CVTB2(ql[kt][2], f2.x - __uint_as_float(qh[kt][2] << 16),
                                 f2.y - __uint_as_float(qh[kt][2] & 0xFFFF0000u));
                CVTB2(ql[kt][3], f3.x - __uint_as_float(qh[kt][3] << 16),
                                 f3.y - __uint_as_float(qh[kt][3] & 0xFFFF0000u));
            }
        }

        float o[8][4];
#pragma unroll
        for (int j = 0; j < 8; ++j) { o[j][0] = o[j][1] = o[j][2] = o[j][3] = 0.f; }
        float m0 = -1e30f, m1 = -1e30f, l0 = 0.f, l1 = 0.f;

        const int ntiles = 17 + qb;

        for (int t = 0; t < ntiles; ++t) {
            __syncthreads();
            const int s0 = t * BK;
            const float* base = (s0 < 1024) ? (cache + (size_t)s0 * ROW3C)
                                            : (qkv + (size_t)(s0 - 1024) * ROW3C);
            // ---- convert K (row-major) and V (transposed) to bf16 hi/lo smem ----
            {
                const int key  = tid >> 1;
                const int half = tid & 1;
                const float* kr = base + (size_t)key * ROW3C + h * 64 + CEMB + half * 32;
                const float* vr = kr + CEMB;
                uint16_t* kh = KHI + key * LDK + half * 32;
                uint16_t* kl = KLO + key * LDK + half * 32;
#pragma unroll
                for (int i = 0; i < 8; ++i) {
                    float4 f = ((const float4*)kr)[i];
                    uint32_t h0, h1, g0, g1;
                    CVTB2(h0, f.x, f.y); CVTB2(h1, f.z, f.w);
                    CVTB2(g0, f.x - __uint_as_float(h0 << 16),
                              f.y - __uint_as_float(h0 & 0xFFFF0000u));
                    CVTB2(g1, f.z - __uint_as_float(h1 << 16),
                              f.w - __uint_as_float(h1 & 0xFFFF0000u));
                    *(uint2*)(kh + i * 4) = make_uint2(h0, h1);
                    *(uint2*)(kl + i * 4) = make_uint2(g0, g1);
                }
#pragma unroll
                for (int i = 0; i < 8; ++i) {
                    float4 f = ((const float4*)vr)[i];
                    const int d0 = half * 32 + i * 4;
                    float vv[4] = {f.x, f.y, f.z, f.w};
#pragma unroll
                    for (int j = 0; j < 4; ++j) {
                        __nv_bfloat16 hb = __float2bfloat16(vv[j]);
                        __nv_bfloat16 lb = __float2bfloat16(vv[j] - __bfloat162float(hb));
                        VHI[(d0 + j) * LDK + key] = *(uint16_t*)&hb;
                        VLO[(d0 + j) * LDK + key] = *(uint16_t*)&lb;
                    }
                }
            }
            __syncthreads();

            // ---- S = Q K^T  (3-pass hi/lo) ----
            float s[8][4];
#pragma unroll
            for (int j = 0; j < 8; ++j) { s[j][0] = s[j][1] = s[j][2] = s[j][3] = 0.f; }
#pragma unroll
            for (int j = 0; j < 8; ++j) {
#pragma unroll
                for (int kt = 0; kt < 4; ++kt) {
                    const int off = (j * 8 + l4) * LDK + kt * 16 + lq2;
                    uint32_t bh0 = *(const uint32_t*)&KHI[off];
                    uint32_t bh1 = *(const uint32_t*)&KHI[off + 8];
                    uint32_t bl0 = *(const uint32_t*)&KLO[off];
                    uint32_t bl1 = *(const uint32_t*)&KLO[off + 8];
                    mma16816(s[j], qh[kt][0], qh[kt][1], qh[kt][2], qh[kt][3], bh0, bh1);
                    mma16816(s[j], qh[kt][0], qh[kt][1], qh[kt][2], qh[kt][3], bl0, bl1);
                    mma16816(s[j], ql[kt][0], ql[kt][1], ql[kt][2], ql[kt][3], bh0, bh1);
                }
            }

            // ---- causal mask on last tile ----
            if (t == ntiles - 1) {
                const int qi0 = w * 16 + l4;
                const int qi1 = qi0 + 8;
#pragma unroll
                for (int j = 0; j < 8; ++j) {
                    const int sj = j * 8 + lq2;
                    if (sj     > qi0) s[j][0] = -1e30f;
                    if (sj + 1 > qi0) s[j][1] = -1e30f;
                    if (sj     > qi1) s[j][2] = -1e30f;
                    if (sj + 1 > qi1) s[j][3] = -1e30f;
                }
            }

            // ---- online softmax (log2 domain) ----
            float mx0 = -1e30f, mx1 = -1e30f;
#pragma unroll
            for (int j = 0; j < 8; ++j) {
                mx0 = fmaxf(mx0, fmaxf(s[j][0], s[j][1]));
                mx1 = fmaxf(mx1, fmaxf(s[j][2], s[j][3]));
            }
            mx0 = fmaxf(mx0, __shfl_xor_sync(0xffffffffu, mx0, 1));
            mx0 = fmaxf(mx0, __shfl_xor_sync(0xffffffffu, mx0, 2));
            mx1 = fmaxf(mx1, __shfl_xor_sync(0xffffffffu, mx1, 1));
            mx1 = fmaxf(mx1, __shfl_xor_sync(0xffffffffu, mx1, 2));
            const float mn0 = fmaxf(m0, mx0);
            const float mn1 = fmaxf(m1, mx1);
            const float a0 = ex2f(m0 - mn0);
            const float a1 = ex2f(m1 - mn1);
            m0 = mn0; m1 = mn1;

            float sum0 = 0.f, sum1 = 0.f;
#pragma unroll
            for (int j = 0; j < 8; ++j) {
                s[j][0] = ex2f(s[j][0] - mn0);
                s[j][1] = ex2f(s[j][1] - mn0);
                s[j][2] = ex2f(s[j][2] - mn1);
                s[j][3] = ex2f(s[j][3] - mn1);
                sum0 += s[j][0] + s[j][1];
                sum1 += s[j][2] + s[j][3];
            }
            l0 = l0 * a0 + sum0;
            l1 = l1 * a1 + sum1;
#pragma unroll
            for (int j = 0; j < 8; ++j) {
                o[j][0] *= a0; o[j][1] *= a0;
                o[j][2] *= a1; o[j][3] *= a1;
            }

            // ---- O += P V  (3-pass hi/lo) ----
#pragma unroll
            for (int kt = 0; kt < 4; ++kt) {
                uint32_t ah0, ah1, ah2, ah3, al0, al1, al2, al3;
                CVTB2(ah0, s[2 * kt][0],     s[2 * kt][1]);
                CVTB2(ah1, s[2 * kt][2],     s[2 * kt][3]);
                CVTB2(ah2, s[2 * kt + 1][0], s[2 * kt + 1][1]);
                CVTB2(ah3, s[2 * kt + 1][2], s[2 * kt + 1][3]);
                CVTB2(al0, s[2 * kt][0]     - __uint_as_float(ah0 << 16),
                           s[2 * kt][1]     - __uint_as_float(ah0 & 0xFFFF0000u));
                CVTB2(al1, s[2 * kt][2]     - __uint_as_float(ah1 << 16),
                           s[2 * kt][3]     - __uint_as_float(ah1 & 0xFFFF0000u));
                CVTB2(al2, s[2 * kt + 1][0] - __uint_as_float(ah2 << 16),
                           s[2 * kt + 1][1] - __uint_as_float(ah2 & 0xFFFF0000u));
                CVTB2(al3, s[2 * kt + 1][2] - __uint_as_float(ah3 << 16),
                           s[2 * kt + 1][3] - __uint_as_float(ah3 & 0xFFFF0000u));
#pragma unroll
                for (int j2 = 0; j2 < 8; ++j2) {
                    const int off = (j2 * 8 + l4) * LDK + kt * 16 + lq2;
                    uint32_t vh0 = *(const uint32_t*)&VHI[off];
                    uint32_t vh1 = *(const uint32_t*)&VHI[off + 8];
                    uint32_t vl0 = *(const uint32_t*)&VLO[off];
                    uint32_t vl1 = *(const uint32_t*)&VLO[off + 8];
                    mma16816(o[j2], ah0, ah1, ah2, ah3, vh0, vh1);
                    mma16816(o[j2], ah0, ah1, ah2, ah3, vl0, vl1);
                    mma16816(o[j2], al0, al1, al2, al3, vh0, vh1);
                }
            }
        }

        // ---- epilogue ----
        l0 += __shfl_xor_sync(0xffffffffu, l0, 1);
        l0 += __shfl_xor_sync(0xffffffffu, l0, 2);
        l1 += __shfl_xor_sync(0xffffffffu, l1, 1);
        l1 += __shfl_xor_sync(0xffffffffu, l1, 2);
        const float inv0 = 1.f / l0;
        const float inv1 = 1.f / l1;
        float* ob0 = out + (size_t)r0 * CEMB + h * 64;
        float* ob1 = ob0 + 8 * CEMB;
#pragma unroll
        for (int j = 0; j < 8; ++j) {
            float2 w0 = make_float2(o[j][0] * inv0, o[j][1] * inv0);
            float2 w1 = make_float2(o[j][2] * inv1, o[j][3] * inv1);
            *(float2*)(ob0 + j * 8 + lq2) = w0;
            *(float2*)(ob1 + j * 8 + lq2) = w1;
        }
    }
}

extern "C" void kernel_launch(void* const* d_in, const int* in_sizes, int n_in,
                              void* d_out, int out_size)
{
    const float* qkv   = (const float*)d_in[0];   // [2048, 3072]
    const float* cache = (const float*)d_in[1];   // [1024, 3072]
    float* out = (float*)d_out;                   // [2048, 1024]

    dim3 grid(16, 16);
    fa_mma_kernel<<<grid, NTH>>>(qkv, cache, out);
}

// round 9
// speedup vs baseline: 4.4270x; 1.2158x over previous
#include <cuda_runtime.h>
#include <cuda_bf16.h>
#include <cstdint>

#define ROW3C  3072
#define CEMB   1024
#define BQ     64
#define BK     64
#define NTH    128
#define LDK    72          // padded row length in bf16 elems
#define LDKB   144         // row pitch in bytes

__device__ __forceinline__ float ex2f(float x) {
    float y; asm("ex2.approx.f32 %0, %1;" : "=f"(y) : "f"(x)); return y;
}
// res.lo = bf16(a), res.hi = bf16(b)
#define CVTB2(res, a, b) \
    asm("cvt.rn.bf16x2.f32 %0, %1, %2;" : "=r"(res) : "f"(b), "f"(a))

__device__ __forceinline__ void mma16816(float c[4],
    uint32_t a0, uint32_t a1, uint32_t a2, uint32_t a3,
    uint32_t b0, uint32_t b1)
{
    asm volatile(
        "mma.sync.aligned.m16n8k16.row.col.f32.bf16.bf16.f32 "
        "{%0,%1,%2,%3}, {%4,%5,%6,%7}, {%8,%9}, {%0,%1,%2,%3};"
        : "+f"(c[0]), "+f"(c[1]), "+f"(c[2]), "+f"(c[3])
        : "r"(a0), "r"(a1), "r"(a2), "r"(a3), "r"(b0), "r"(b1));
}

__device__ __forceinline__ void ldsm4(uint32_t& r0, uint32_t& r1, uint32_t& r2, uint32_t& r3,
                                      uint32_t addr)
{
    asm volatile("ldmatrix.sync.aligned.m8n8.x4.shared.b16 {%0,%1,%2,%3}, [%4];"
        : "=r"(r0), "=r"(r1), "=r"(r2), "=r"(r3) : "r"(addr));
}
__device__ __forceinline__ void ldsm4t(uint32_t& r0, uint32_t& r1, uint32_t& r2, uint32_t& r3,
                                       uint32_t addr)
{
    asm volatile("ldmatrix.sync.aligned.m8n8.x4.trans.shared.b16 {%0,%1,%2,%3}, [%4];"
        : "=r"(r0), "=r"(r1), "=r"(r2), "=r"(r3) : "r"(addr));
}

__global__ __launch_bounds__(NTH, 2)
void fa_mma_kernel(const float* __restrict__ qkv,
                   const float* __restrict__ cache,
                   float* __restrict__ out)
{
    __shared__ __align__(16) uint16_t KHI[BK * LDK];
    __shared__ __align__(16) uint16_t KLO[BK * LDK];
    __shared__ __align__(16) uint16_t VHI[BK * LDK];   // row-major [key][dim]
    __shared__ __align__(16) uint16_t VLO[BK * LDK];

    const int tid  = threadIdx.x;
    const int w    = tid >> 5;
    const int lane = tid & 31;
    const int l4   = lane >> 2;
    const int lq2  = (lane & 3) * 2;
    const int h    = blockIdx.y;
    const int bx   = blockIdx.x;

    // per-lane ldmatrix offsets (bytes)
    const uint32_t khi_b = (uint32_t)__cvta_generic_to_shared(KHI);
    const uint32_t klo_b = (uint32_t)__cvta_generic_to_shared(KLO);
    const uint32_t vhi_b = (uint32_t)__cvta_generic_to_shared(VHI);
    const uint32_t vlo_b = (uint32_t)__cvta_generic_to_shared(VLO);
    // QK (non-trans): lanes 0-7 rows n0..7 khalf0, 8-15 khalf1, 16-23 n8..15 khalf0, 24-31 khalf1
    const uint32_t offK = ((lane & 7) + ((lane & 16) >> 1)) * LDKB + ((lane & 8) << 1);
    // PV (trans): lanes 0-15 keys 0..15 dimcol0, lanes 16-31 same keys dimcol+16B
    const uint32_t offV = (lane & 15) * LDKB + ((lane & 16));

    for (int phse = 0; phse < 2; ++phse) {
        const int qb = phse ? (31 - bx) : bx;

        // ---- Q fragments (regs, whole phase) ----
        const float scl = 0.125f * 1.44269504f;
        const int r0 = qb * BQ + w * 16 + l4;
        uint32_t qh[4][4], ql[4][4];
        {
            const float* q0 = qkv + (size_t)r0 * ROW3C + h * 64;
            const float* q1 = q0 + 8 * ROW3C;
#pragma unroll
            for (int kt = 0; kt < 4; ++kt) {
                float2 f0 = *(const float2*)(q0 + kt * 16 + lq2);
                float2 f1 = *(const float2*)(q1 + kt * 16 + lq2);
                float2 f2 = *(const float2*)(q0 + kt * 16 + 8 + lq2);
                float2 f3 = *(const float2*)(q1 + kt * 16 + 8 + lq2);
                f0.x *= scl; f0.y *= scl; f1.x *= scl; f1.y *= scl;
                f2.x *= scl; f2.y *= scl; f3.x *= scl; f3.y *= scl;
                CVTB2(qh[kt][0], f0.x, f0.y);
                CVTB2(qh[kt][1], f1.x, f1.y);
                CVTB2(qh[kt][2], f2.x, f2.y);
                CVTB2(qh[kt][3], f3.x, f3.y);
                CVTB2(ql[kt][0], f0.x - __uint_as_float(qh[kt][0] << 16),
                                 f0.y - __uint_as_float(qh[kt][0] & 0xFFFF0000u));
                CVTB2(ql[kt][1], f1.x - __uint_as_float(qh[kt][1] << 16),
                                 f1.y - __uint_as_float(qh[kt][1] & 0xFFFF0000u));
                CVTB2(ql[kt][2], f2.x - __uint_as_float(qh[kt][2] << 16),
                                 f2.y - __uint_as_float(qh[kt][2] & 0xFFFF0000u));
                CVTB2(ql[kt][3], f3.x - __uint_as_float(qh[kt][3] << 16),
                                 f3.y - __uint_as_float(qh[kt][3] & 0xFFFF0000u));
            }
        }

        float o[8][4];
#pragma unroll
        for (int j = 0; j < 8; ++j) { o[j][0] = o[j][1] = o[j][2] = o[j][3] = 0.f; }
        float m0 = -1e30f, m1 = -1e30f, l0 = 0.f, l1 = 0.f;

        const int ntiles = 17 + qb;

        for (int t = 0; t < ntiles; ++t) {
            __syncthreads();
            const int s0 = t * BK;
            const float* base = (s0 < 1024) ? (cache + (size_t)s0 * ROW3C)
                                            : (qkv + (size_t)(s0 - 1024) * ROW3C);
            // ---- convert K and V (both row-major) to bf16 hi/lo ----
            {
                const int key  = tid >> 1;
                const int half = tid & 1;
                const float* kr = base + (size_t)key * ROW3C + h * 64 + CEMB + half * 32;
                const float* vr = kr + CEMB;
                uint16_t* kh = KHI + key * LDK + half * 32;
                uint16_t* kl = KLO + key * LDK + half * 32;
                uint16_t* vh = VHI + key * LDK + half * 32;
                uint16_t* vl = VLO + key * LDK + half * 32;
#pragma unroll
                for (int i = 0; i < 8; ++i) {
                    float4 f = ((const float4*)kr)[i];
                    uint32_t h0, h1, g0, g1;
                    CVTB2(h0, f.x, f.y); CVTB2(h1, f.z, f.w);
                    CVTB2(g0, f.x - __uint_as_float(h0 << 16),
                              f.y - __uint_as_float(h0 & 0xFFFF0000u));
                    CVTB2(g1, f.z - __uint_as_float(h1 << 16),
                              f.w - __uint_as_float(h1 & 0xFFFF0000u));
                    *(uint2*)(kh + i * 4) = make_uint2(h0, h1);
                    *(uint2*)(kl + i * 4) = make_uint2(g0, g1);
                }
#pragma unroll
                for (int i = 0; i < 8; ++i) {
                    float4 f = ((const float4*)vr)[i];
                    uint32_t h0, h1, g0, g1;
                    CVTB2(h0, f.x, f.y); CVTB2(h1, f.z, f.w);
                    CVTB2(g0, f.x - __uint_as_float(h0 << 16),
                              f.y - __uint_as_float(h0 & 0xFFFF0000u));
                    CVTB2(g1, f.z - __uint_as_float(h1 << 16),
                              f.w - __uint_as_float(h1 & 0xFFFF0000u));
                    *(uint2*)(vh + i * 4) = make_uint2(h0, h1);
                    *(uint2*)(vl + i * 4) = make_uint2(g0, g1);
                }
            }
            __syncthreads();

            // ---- S = Q K^T (3-pass hi/lo), ldmatrix B-frags ----
            float s[8][4];
#pragma unroll
            for (int j = 0; j < 8; ++j) { s[j][0] = s[j][1] = s[j][2] = s[j][3] = 0.f; }
#pragma unroll
            for (int kt = 0; kt < 4; ++kt) {
#pragma unroll
                for (int jp = 0; jp < 4; ++jp) {
                    const uint32_t ao = (uint32_t)(jp * 16 * LDKB + kt * 32) + offK;
                    uint32_t bh0, bh1, bh2, bh3, bl0, bl1, bl2, bl3;
                    ldsm4(bh0, bh1, bh2, bh3, khi_b + ao);
                    ldsm4(bl0, bl1, bl2, bl3, klo_b + ao);
                    mma16816(s[2*jp],   qh[kt][0], qh[kt][1], qh[kt][2], qh[kt][3], bh0, bh1);
                    mma16816(s[2*jp],   qh[kt][0], qh[kt][1], qh[kt][2], qh[kt][3], bl0, bl1);
                    mma16816(s[2*jp],   ql[kt][0], ql[kt][1], ql[kt][2], ql[kt][3], bh0, bh1);
                    mma16816(s[2*jp+1], qh[kt][0], qh[kt][1], qh[kt][2], qh[kt][3], bh2, bh3);
                    mma16816(s[2*jp+1], qh[kt][0], qh[kt][1], qh[kt][2], qh[kt][3], bl2, bl3);
                    mma16816(s[2*jp+1], ql[kt][0], ql[kt][1], ql[kt][2], ql[kt][3], bh2, bh3);
                }
            }

            if (t == ntiles - 1) {
                const int qi0 = w * 16 + l4;
                const int qi1 = qi0 + 8;
#pragma unroll
                for (int j = 0; j < 8; ++j) {
                    const int sj = j * 8 + lq2;
                    if (sj     > qi0) s[j][0] = -1e30f;
                    if (sj + 1 > qi0) s[j][1] = -1e30f;
                    if (sj     > qi1) s[j][2] = -1e30f;
                    if (sj + 1 > qi1) s[j][3] = -1e30f;
                }
            }

            // ---- online softmax (log2 domain) ----
            float mx0 = -1e30f, mx1 = -1e30f;
#pragma unroll
            for (int j = 0; j < 8; ++j) {
                mx0 = fmaxf(mx0, fmaxf(s[j][0], s[j][1]));
                mx1 = fmaxf(mx1, fmaxf(s[j][2], s[j][3]));
            }
            mx0 = fmaxf(mx0, __shfl_xor_sync(0xffffffffu, mx0, 1));
            mx0 = fmaxf(mx0, __shfl_xor_sync(0xffffffffu, mx0, 2));
            mx1 = fmaxf(mx1, __shfl_xor_sync(0xffffffffu, mx1, 1));
            mx1 = fmaxf(mx1, __shfl_xor_sync(0xffffffffu, mx1, 2));
            const float mn0 = fmaxf(m0, mx0);
            const float mn1 = fmaxf(m1, mx1);
            const float a0 = ex2f(m0 - mn0);
            const float a1 = ex2f(m1 - mn1);
            m0 = mn0; m1 = mn1;

            float sum0 = 0.f, sum1 = 0.f;
#pragma unroll
            for (int j = 0; j < 8; ++j) {
                s[j][0] = ex2f(s[j][0] - mn0);
                s[j][1] = ex2f(s[j][1] - mn0);
                s[j][2] = ex2f(s[j][2] - mn1);
                s[j][3] = ex2f(s[j][3] - mn1);
                sum0 += s[j][0] + s[j][1];
                sum1 += s[j][2] + s[j][3];
            }
            l0 = l0 * a0 + sum0;
            l1 = l1 * a1 + sum1;
#pragma unroll
            for (int j = 0; j < 8; ++j) {
                o[j][0] *= a0; o[j][1] *= a0;
                o[j][2] *= a1; o[j][3] *= a1;
            }

            // ---- O += P V (3-pass hi/lo), ldmatrix.trans B-frags ----
#pragma unroll
            for (int kt = 0; kt < 4; ++kt) {
                uint32_t ah0, ah1, ah2, ah3, al0, al1, al2, al3;
                CVTB2(ah0, s[2 * kt][0],     s[2 * kt][1]);
                CVTB2(ah1, s[2 * kt][2],     s[2 * kt][3]);
                CVTB2(ah2, s[2 * kt + 1][0], s[2 * kt + 1][1]);
                CVTB2(ah3, s[2 * kt + 1][2], s[2 * kt + 1][3]);
                CVTB2(al0, s[2 * kt][0]     - __uint_as_float(ah0 << 16),
                           s[2 * kt][1]     - __uint_as_float(ah0 & 0xFFFF0000u));
                CVTB2(al1, s[2 * kt][2]     - __uint_as_float(ah1 << 16),
                           s[2 * kt][3]     - __uint_as_float(ah1 & 0xFFFF0000u));
                CVTB2(al2, s[2 * kt + 1][0] - __uint_as_float(ah2 << 16),
                           s[2 * kt + 1][1] - __uint_as_float(ah2 & 0xFFFF0000u));
                CVTB2(al3, s[2 * kt + 1][2] - __uint_as_float(ah3 << 16),
                           s[2 * kt + 1][3] - __uint_as_float(ah3 & 0xFFFF0000u));
#pragma unroll
                for (int jp = 0; jp < 4; ++jp) {
                    const uint32_t ao = (uint32_t)(kt * 16 * LDKB + jp * 32) + offV;
                    uint32_t vh0, vh1, vh2, vh3, vl0, vl1, vl2, vl3;
                    ldsm4t(vh0, vh1, vh2, vh3, vhi_b + ao);
                    ldsm4t(vl0, vl1, vl2, vl3, vlo_b + ao);
                    mma16816(o[2*jp],   ah0, ah1, ah2, ah3, vh0, vh1);
                    mma16816(o[2*jp],   ah0, ah1, ah2, ah3, vl0, vl1);
                    mma16816(o[2*jp],   al0, al1, al2, al3, vh0, vh1);
                    mma16816(o[2*jp+1], ah0, ah1, ah2, ah3, vh2, vh3);
                    mma16816(o[2*jp+1], ah0, ah1, ah2, ah3, vl2, vl3);
                    mma16816(o[2*jp+1], al0, al1, al2, al3, vh2, vh3);
                }
            }
        }

        // ---- epilogue ----
        l0 += __shfl_xor_sync(0xffffffffu, l0, 1);
        l0 += __shfl_xor_sync(0xffffffffu, l0, 2);
        l1 += __shfl_xor_sync(0xffffffffu, l1, 1);
        l1 += __shfl_xor_sync(0xffffffffu, l1, 2);
        const float inv0 = 1.f / l0;
        const float inv1 = 1.f / l1;
        float* ob0 = out + (size_t)r0 * CEMB + h * 64;
        float* ob1 = ob0 + 8 * CEMB;
#pragma unroll
        for (int j = 0; j < 8; ++j) {
            float2 w0 = make_float2(o[j][0] * inv0, o[j][1] * inv0);
            float2 w1 = make_float2(o[j][2] * inv1, o[j][3] * inv1);
            *(float2*)(ob0 + j * 8 + lq2) = w0;
            *(float2*)(ob1 + j * 8 + lq2) = w1;
        }
    }
}

extern "C" void kernel_launch(void* const* d_in, const int* in_sizes, int n_in,
                              void* d_out, int out_size)
{
    const float* qkv   = (const float*)d_in[0];   // [2048, 3072]
    const float* cache = (const float*)d_in[1];   // [1024, 3072]
    float* out = (float*)d_out;                   // [2048, 1024]

    dim3 grid(16, 16);
    fa_mma_kernel<<<grid, NTH>>>(qkv, cache, out);
}

// round 10
// speedup vs baseline: 7.6424x; 1.7263x over previous
#include <cuda_runtime.h>
#include <cuda_bf16.h>
#include <cstdint>

#define ROW3C  3072
#define CEMB   1024
#define NKEY   3072
#define BQ     64
#define BK     64
#define NTH    128
#define TILE_B 32768          // 4 tensors x 8KB per tile buffer
#define SMEM_DYN (2 * TILE_B)

// pre-converted bf16 hi/lo K and V, layout [head][key][64]
__device__ __align__(16) __nv_bfloat16 KHI_G[16 * NKEY * 64];
__device__ __align__(16) __nv_bfloat16 KLO_G[16 * NKEY * 64];
__device__ __align__(16) __nv_bfloat16 VHI_G[16 * NKEY * 64];
__device__ __align__(16) __nv_bfloat16 VLO_G[16 * NKEY * 64];

__device__ __forceinline__ float ex2f(float x) {
    float y; asm("ex2.approx.f32 %0, %1;" : "=f"(y) : "f"(x)); return y;
}
// res.lo = bf16(a), res.hi = bf16(b)
#define CVTB2(res, a, b) \
    asm("cvt.rn.bf16x2.f32 %0, %1, %2;" : "=r"(res) : "f"(b), "f"(a))

__device__ __forceinline__ void mma16816(float c[4],
    uint32_t a0, uint32_t a1, uint32_t a2, uint32_t a3,
    uint32_t b0, uint32_t b1)
{
    asm volatile(
        "mma.sync.aligned.m16n8k16.row.col.f32.bf16.bf16.f32 "
        "{%0,%1,%2,%3}, {%4,%5,%6,%7}, {%8,%9}, {%0,%1,%2,%3};"
        : "+f"(c[0]), "+f"(c[1]), "+f"(c[2]), "+f"(c[3])
        : "r"(a0), "r"(a1), "r"(a2), "r"(a3), "r"(b0), "r"(b1));
}
__device__ __forceinline__ void ldsm4(uint32_t& r0, uint32_t& r1, uint32_t& r2, uint32_t& r3,
                                      uint32_t addr)
{
    asm volatile("ldmatrix.sync.aligned.m8n8.x4.shared.b16 {%0,%1,%2,%3}, [%4];"
        : "=r"(r0), "=r"(r1), "=r"(r2), "=r"(r3) : "r"(addr));
}
__device__ __forceinline__ void ldsm4t(uint32_t& r0, uint32_t& r1, uint32_t& r2, uint32_t& r3,
                                       uint32_t addr)
{
    asm volatile("ldmatrix.sync.aligned.m8n8.x4.trans.shared.b16 {%0,%1,%2,%3}, [%4];"
        : "=r"(r0), "=r"(r1), "=r"(r2), "=r"(r3) : "r"(addr));
}

// ---------------- pre-conversion kernel ----------------
__global__ void conv_kernel(const float* __restrict__ qkv,
                            const float* __restrict__ cache)
{
    const int idx = blockIdx.x * 256 + threadIdx.x;   // [0, 3072*256)
    const int s  = idx >> 8;
    const int q4 = idx & 255;                          // float4 index within 1024 dims
    const float* row = (s < 1024) ? cache + (size_t)s * ROW3C
                                  : qkv + (size_t)(s - 1024) * ROW3C;
    const int h  = q4 >> 4;
    const int d4 = q4 & 15;
    const size_t off = (((size_t)h * NKEY + s) << 6) + (size_t)d4 * 4;

    float4 k = *(const float4*)(row + CEMB + q4 * 4);
    uint32_t h0, h1, g0, g1;
    CVTB2(h0, k.x, k.y); CVTB2(h1, k.z, k.w);
    CVTB2(g0, k.x - __uint_as_float(h0 << 16), k.y - __uint_as_float(h0 & 0xFFFF0000u));
    CVTB2(g1, k.z - __uint_as_float(h1 << 16), k.w - __uint_as_float(h1 & 0xFFFF0000u));
    *(uint2*)(KHI_G + off) = make_uint2(h0, h1);
    *(uint2*)(KLO_G + off) = make_uint2(g0, g1);

    float4 v = *(const float4*)(row + 2 * CEMB + q4 * 4);
    CVTB2(h0, v.x, v.y); CVTB2(h1, v.z, v.w);
    CVTB2(g0, v.x - __uint_as_float(h0 << 16), v.y - __uint_as_float(h0 & 0xFFFF0000u));
    CVTB2(g1, v.z - __uint_as_float(h1 << 16), v.w - __uint_as_float(h1 & 0xFFFF0000u));
    *(uint2*)(VHI_G + off) = make_uint2(h0, h1);
    *(uint2*)(VLO_G + off) = make_uint2(g0, g1);
}

// ---------------- tile prefetch: 32KB via cp.async ----------------
__device__ __forceinline__ void prefetch_tile(uint32_t buf, int hbase, int s0, int tid)
{
#pragma unroll
    for (int i = 0; i < 4; ++i) {
        const __nv_bfloat16* g = (i == 0) ? KHI_G : (i == 1) ? KLO_G
                               : (i == 2) ? VHI_G : VLO_G;
#pragma unroll
        for (int j = 0; j < 4; ++j) {
            const int c   = tid + j * 128;         // 0..511 chunk within tensor
            const int r   = c >> 3;                // key row 0..63
            const int col = c & 7;                 // 16B column 0..7
            const __nv_bfloat16* src = g + (((size_t)(hbase + s0 + r)) << 6) + (col << 3);
            const uint32_t dst = buf + i * 8192 + r * 128 + ((col ^ (r & 7)) << 4);
            asm volatile("cp.async.cg.shared.global [%0], [%1], 16;\n"
                :: "r"(dst), "l"(src));
        }
    }
}

__global__ __launch_bounds__(NTH, 2)
void fa_mma2_kernel(const float* __restrict__ qkv,
                    float* __restrict__ out)
{
    extern __shared__ __align__(128) char smem[];
    const uint32_t sb = (uint32_t)__cvta_generic_to_shared(smem);

    const int tid  = threadIdx.x;
    const int w    = tid >> 5;
    const int lane = tid & 31;
    const int l4   = lane >> 2;
    const int lq2  = (lane & 3) * 2;
    const int h    = blockIdx.y;
    const int bx   = blockIdx.x;
    const int hbase = h * NKEY;

    // ldmatrix per-lane constants
    const int rbK  = (lane & 7) + ((lane & 16) >> 1);   // 0..15 row-within-16
    const int ckK  = (lane >> 3) & 1;                   // k 16B-col select
    const int keyV = lane & 15;                         // key-within-16 (trans)
    const int cvV  = (lane >> 4) & 1;
    const int sxK  = lane & 7;                          // swizzle keys

    for (int phse = 0; phse < 2; ++phse) {
        const int qb = phse ? (31 - bx) : bx;
        const int ntiles = 17 + qb;

        prefetch_tile(sb, hbase, 0, tid);
        asm volatile("cp.async.commit_group;\n");

        // ---- Q fragments (regs, whole phase) ----
        const float scl = 0.125f * 1.44269504f;
        const int r0 = qb * BQ + w * 16 + l4;
        uint32_t qh[4][4], ql[4][4];
        {
            const float* q0 = qkv + (size_t)r0 * ROW3C + h * 64;
            const float* q1 = q0 + 8 * ROW3C;
#pragma unroll
            for (int kt = 0; kt < 4; ++kt) {
                float2 f0 = *(const float2*)(q0 + kt * 16 + lq2);
                float2 f1 = *(const float2*)(q1 + kt * 16 + lq2);
                float2 f2 = *(const float2*)(q0 + kt * 16 + 8 + lq2);
                float2 f3 = *(const float2*)(q1 + kt * 16 + 8 + lq2);
                f0.x *= scl; f0.y *= scl; f1.x *= scl; f1.y *= scl;
                f2.x *= scl; f2.y *= scl; f3.x *= scl; f3.y *= scl;
                CVTB2(qh[kt][0], f0.x, f0.y);
                CVTB2(qh[kt][1], f1.x, f1.y);
                CVTB2(qh[kt][2], f2.x, f2.y);
                CVTB2(qh[kt][3], f3.x, f3.y);
                CVTB2(ql[kt][0], f0.x - __uint_as_float(qh[kt][0] << 16),
                                 f0.y - __uint_as_float(qh[kt][0] & 0xFFFF0000u));
                CVTB2(ql[kt][1], f1.x - __uint_as_float(qh[kt][1] << 16),
                                 f1.y - __uint_as_float(qh[kt][1] & 0xFFFF0000u));
                CVTB2(ql[kt][2], f2.x - __uint_as_float(qh[kt][2] << 16),
                                 f2.y - __uint_as_float(qh[kt][2] & 0xFFFF0000u));
                CVTB2(ql[kt][3], f3.x - __uint_as_float(qh[kt][3] << 16),
                                 f3.y - __uint_as_float(qh[kt][3] & 0xFFFF0000u));
            }
        }

        float o[8][4];
#pragma unroll
        for (int j = 0; j < 8; ++j) { o[j][0] = o[j][1] = o[j][2] = o[j][3] = 0.f; }
        float m0 = -1e30f, m1 = -1e30f, l0 = 0.f, l1 = 0.f;

        for (int t = 0; t < ntiles; ++t) {
            if (t + 1 < ntiles)
                prefetch_tile(sb + ((t + 1) & 1) * TILE_B, hbase, (t + 1) * BK, tid);
            asm volatile("cp.async.commit_group;\n");
            asm volatile("cp.async.wait_group 1;\n");
            __syncthreads();

            const uint32_t buf = sb + (t & 1) * TILE_B;

            // ---- S = Q K^T (3-pass hi/lo) ----
            float s[8][4];
#pragma unroll
            for (int j = 0; j < 8; ++j) { s[j][0] = s[j][1] = s[j][2] = s[j][3] = 0.f; }
#pragma unroll
            for (int kt = 0; kt < 4; ++kt) {
#pragma unroll
                for (int jp = 0; jp < 4; ++jp) {
                    const int r = jp * 16 + rbK;
                    const uint32_t ao = buf + (uint32_t)r * 128u
                                      + (uint32_t)(((kt * 2 + ckK) ^ sxK) << 4);
                    uint32_t bh0, bh1, bh2, bh3, bl0, bl1, bl2, bl3;
                    ldsm4(bh0, bh1, bh2, bh3, ao);
                    ldsm4(bl0, bl1, bl2, bl3, ao + 8192);
                    mma16816(s[2*jp],   qh[kt][0], qh[kt][1], qh[kt][2], qh[kt][3], bh0, bh1);
                    mma16816(s[2*jp],   qh[kt][0], qh[kt][1], qh[kt][2], qh[kt][3], bl0, bl1);
                    mma16816(s[2*jp],   ql[kt][0], ql[kt][1], ql[kt][2], ql[kt][3], bh0, bh1);
                    mma16816(s[2*jp+1], qh[kt][0], qh[kt][1], qh[kt][2], qh[kt][3], bh2, bh3);
                    mma16816(s[2*jp+1], qh[kt][0], qh[kt][1], qh[kt][2], qh[kt][3], bl2, bl3);
                    mma16816(s[2*jp+1], ql[kt][0], ql[kt][1], ql[kt][2], ql[kt][3], bh2, bh3);
                }
            }

            if (t == ntiles - 1) {
                const int qi0 = w * 16 + l4;
                const int qi1 = qi0 + 8;
#pragma unroll
                for (int j = 0; j < 8; ++j) {
                    const int sj = j * 8 + lq2;
                    if (sj     > qi0) s[j][0] = -1e30f;
                    if (sj + 1 > qi0) s[j][1] = -1e30f;
                    if (sj     > qi1) s[j][2] = -1e30f;
                    if (sj + 1 > qi1) s[j][3] = -1e30f;
                }
            }

            // ---- online softmax (log2 domain) ----
            float mx0 = -1e30f, mx1 = -1e30f;
#pragma unroll
            for (int j = 0; j < 8; ++j) {
                mx0 = fmaxf(mx0, fmaxf(s[j][0], s[j][1]));
                mx1 = fmaxf(mx1, fmaxf(s[j][2], s[j][3]));
            }
            mx0 = fmaxf(mx0, __shfl_xor_sync(0xffffffffu, mx0, 1));
            mx0 = fmaxf(mx0, __shfl_xor_sync(0xffffffffu, mx0, 2));
            mx1 = fmaxf(mx1, __shfl_xor_sync(0xffffffffu, mx1, 1));
            mx1 = fmaxf(mx1, __shfl_xor_sync(0xffffffffu, mx1, 2));
            const float mn0 = fmaxf(m0, mx0);
            const float mn1 = fmaxf(m1, mx1);
            const float a0 = ex2f(m0 - mn0);
            const float a1 = ex2f(m1 - mn1);
            m0 = mn0; m1 = mn1;

            float sum0 = 0.f, sum1 = 0.f;
#pragma unroll
            for (int j = 0; j < 8; ++j) {
                s[j][0] = ex2f(s[j][0] - mn0);
                s[j][1] = ex2f(s[j][1] - mn0);
                s[j][2] = ex2f(s[j][2] - mn1);
                s[j][3] = ex2f(s[j][3] - mn1);
                sum0 += s[j][0] + s[j][1];
                sum1 += s[j][2] + s[j][3];
            }
            l0 = l0 * a0 + sum0;
            l1 = l1 * a1 + sum1;
#pragma unroll
            for (int j = 0; j < 8; ++j) {
                o[j][0] *= a0; o[j][1] *= a0;
                o[j][2] *= a1; o[j][3] *= a1;
            }

            // ---- O += P V (3-pass hi/lo) ----
#pragma unroll
            for (int kt = 0; kt < 4; ++kt) {
                uint32_t ah0, ah1, ah2, ah3, al0, al1, al2, al3;
                CVTB2(ah0, s[2 * kt][0],     s[2 * kt][1]);
                CVTB2(ah1, s[2 * kt][2],     s[2 * kt][3]);
                CVTB2(ah2, s[2 * kt + 1][0], s[2 * kt + 1][1]);
                CVTB2(ah3, s[2 * kt + 1][2], s[2 * kt + 1][3]);
                CVTB2(al0, s[2 * kt][0]     - __uint_as_float(ah0 << 16),
                           s[2 * kt][1]     - __uint_as_float(ah0 & 0xFFFF0000u));
                CVTB2(al1, s[2 * kt][2]     - __uint_as_float(ah1 << 16),
                           s[2 * kt][3]     - __uint_as_float(ah1 & 0xFFFF0000u));
                CVTB2(al2, s[2 * kt + 1][0] - __uint_as_float(ah2 << 16),
                           s[2 * kt + 1][1] - __uint_as_float(ah2 & 0xFFFF0000u));
                CVTB2(al3, s[2 * kt + 1][2] - __uint_as_float(ah3 << 16),
                           s[2 * kt + 1][3] - __uint_as_float(ah3 & 0xFFFF0000u));
#pragma unroll
                for (int jp = 0; jp < 4; ++jp) {
                    const int key = kt * 16 + keyV;
                    const uint32_t ao = buf + 16384u + (uint32_t)key * 128u
                                      + (uint32_t)(((jp * 2 + cvV) ^ sxK) << 4);
                    uint32_t vh0, vh1, vh2, vh3, vl0, vl1, vl2, vl3;
                    ldsm4t(vh0, vh1, vh2, vh3, ao);
                    ldsm4t(vl0, vl1, vl2, vl3, ao + 8192);
                    mma16816(o[2*jp],   ah0, ah1, ah2, ah3, vh0, vh1);
                    mma16816(o[2*jp],   ah0, ah1, ah2, ah3, vl0, vl1);
                    mma16816(o[2*jp],   al0, al1, al2, al3, vh0, vh1);
                    mma16816(o[2*jp+1], ah0, ah1, ah2, ah3, vh2, vh3);
                    mma16816(o[2*jp+1], ah0, ah1, ah2, ah3, vl2, vl3);
                    mma16816(o[2*jp+1], al0, al1, al2, al3, vh2, vh3);
                }
            }
            __syncthreads();
        }

        // ---- epilogue ----
        l0 += __shfl_xor_sync(0xffffffffu, l0, 1);
        l0 += __shfl_xor_sync(0xffffffffu, l0, 2);
        l1 += __shfl_xor_sync(0xffffffffu, l1, 1);
        l1 += __shfl_xor_sync(0xffffffffu, l1, 2);
        const float inv0 = 1.f / l0;
        const float inv1 = 1.f / l1;
        float* ob0 = out + (size_t)r0 * CEMB + h * 64;
        float* ob1 = ob0 + 8 * CEMB;
#pragma unroll
        for (int j = 0; j < 8; ++j) {
            float2 w0 = make_float2(o[j][0] * inv0, o[j][1] * inv0);
            float2 w1 = make_float2(o[j][2] * inv1, o[j][3] * inv1);
            *(float2*)(ob0 + j * 8 + lq2) = w0;
            *(float2*)(ob1 + j * 8 + lq2) = w1;
        }
    }
}

extern "C" void kernel_launch(void* const* d_in, const int* in_sizes, int n_in,
                              void* d_out, int out_size)
{
    const float* qkv   = (const float*)d_in[0];   // [2048, 3072]
    const float* cache = (const float*)d_in[1];   // [1024, 3072]
    float* out = (float*)d_out;                   // [2048, 1024]

    static bool attr_set = false;
    if (!attr_set) {
        cudaFuncSetAttribute(fa_mma2_kernel,
                             cudaFuncAttributeMaxDynamicSharedMemorySize, SMEM_DYN);
        attr_set = true;
    }

    conv_kernel<<<NKEY, 256>>>(qkv, cache);
    dim3 grid(16, 16);
    fa_mma2_kernel<<<grid, NTH, SMEM_DYN>>>(qkv, out);
}